// round 5
// baseline (speedup 1.0000x reference)
#include <cuda_runtime.h>
#include <cuda_bf16.h>
#include <cstdint>

#define NN   65536
#define INC  512
#define HD   1024
#define DIM  256

// ---------------- scratch (device globals) -----------------------------------
__device__ __nv_bfloat16 g_xb[NN * INC];
__device__ __nv_bfloat16 g_wb[3][INC * HD];
__device__ __nv_bfloat16 g_q[NN * HD];
__device__ __nv_bfloat16 g_k[NN * HD];
__device__ __nv_bfloat16 g_v[NN * HD];
__device__ float g_colsum_p[512 * INC];
__device__ float g_colsum[INC];
__device__ float g_vsum[HD];
__device__ float g_ksum_p[64 * HD];
__device__ float g_ksum[HD];
__device__ float g_kv_part[16 * 4 * DIM * DIM];
__device__ __nv_bfloat16 g_kvb[4 * DIM * DIM];   // stacked [h*256+m][256]
__device__ float g_invden[NN * 4];

// ---------------- helpers ----------------------------------------------------
__device__ __forceinline__ uint32_t smem_u32(const void* p) {
    return (uint32_t)__cvta_generic_to_shared(p);
}
__device__ __forceinline__ void ldsm4(uint32_t* r, uint32_t a) {
    asm volatile("ldmatrix.sync.aligned.m8n8.x4.shared.b16 {%0,%1,%2,%3}, [%4];"
        : "=r"(r[0]), "=r"(r[1]), "=r"(r[2]), "=r"(r[3]) : "r"(a));
}
__device__ __forceinline__ void ldsm4t(uint32_t* r, uint32_t a) {
    asm volatile("ldmatrix.sync.aligned.m8n8.x4.trans.shared.b16 {%0,%1,%2,%3}, [%4];"
        : "=r"(r[0]), "=r"(r[1]), "=r"(r[2]), "=r"(r[3]) : "r"(a));
}
__device__ __forceinline__ void mma16816(float* d, const uint32_t* a, const uint32_t* b) {
    asm volatile("mma.sync.aligned.m16n8k16.row.col.f32.bf16.bf16.f32 "
        "{%0,%1,%2,%3}, {%4,%5,%6,%7}, {%8,%9}, {%0,%1,%2,%3};"
        : "+f"(d[0]), "+f"(d[1]), "+f"(d[2]), "+f"(d[3])
        : "r"(a[0]), "r"(a[1]), "r"(a[2]), "r"(a[3]), "r"(b[0]), "r"(b[1]));
}
__device__ __forceinline__ void cp16(void* s, const void* g) {
    asm volatile("cp.async.cg.shared.global [%0], [%1], 16;"
        :: "r"(smem_u32(s)), "l"(g));
}
__device__ __forceinline__ void cp_commit() { asm volatile("cp.async.commit_group;"); }
template<int W> __device__ __forceinline__ void cp_wait() {
    asm volatile("cp.async.wait_group %0;" :: "n"(W));
}

// ---------------- cvt_x + colsum partials (fused) ----------------------------
__global__ void cvt_x_kernel(const float* __restrict__ x) {
    int p = blockIdx.x;                 // 256 blocks, 256 rows each
    int tid = threadIdx.x;              // 256
    int seg = tid & 127, half = tid >> 7;
    size_t r0 = (size_t)p * 256;
    float c0 = 0.f, c1 = 0.f, c2 = 0.f, c3 = 0.f;
    for (int i = half; i < 256; i += 2) {
        float4 f = ((const float4*)x)[(r0 + i) * 128 + seg];
        c0 += f.x; c1 += f.y; c2 += f.z; c3 += f.w;
        __nv_bfloat162* d = (__nv_bfloat162*)g_xb + (r0 + i) * 256 + seg * 2;
        d[0] = __floats2bfloat162_rn(f.x, f.y);
        d[1] = __floats2bfloat162_rn(f.z, f.w);
    }
    float* dst = &g_colsum_p[(p * 2 + half) * INC + seg * 4];
    dst[0] = c0; dst[1] = c1; dst[2] = c2; dst[3] = c3;
}
__global__ void colsum_red_kernel() {
    int c = blockIdx.x * 256 + threadIdx.x;     // grid.x = 2
    float s = 0.f;
    for (int p = 0; p < 512; p++) s += g_colsum_p[p * INC + c];
    g_colsum[c] = s;
}
__global__ void vsum_kernel(const float* __restrict__ Wv, const float* __restrict__ bv) {
    int warp = threadIdx.x >> 5, lane = threadIdx.x & 31;
    int m = blockIdx.x * 8 + warp;               // grid = 128
    float s = 0.f;
    for (int kk = lane; kk < INC; kk += 32) s += g_colsum[kk] * Wv[kk * HD + m];
    #pragma unroll
    for (int o = 16; o > 0; o >>= 1) s += __shfl_xor_sync(0xffffffffu, s, o);
    if (lane == 0) g_vsum[m] = s + 65536.f * bv[m];
}

__global__ void cvt_w_kernel(const float* __restrict__ Wq,
                             const float* __restrict__ Wk,
                             const float* __restrict__ Wv) {
    int which = blockIdx.y;
    const float* src = which == 0 ? Wq : which == 1 ? Wk : Wv;
    int i = blockIdx.x * 256 + threadIdx.x;      // grid.x = 512
    float4 f = ((const float4*)src)[i];
    __nv_bfloat162* d2 = (__nv_bfloat162*)g_wb[which];
    d2[2 * i]     = __floats2bfloat162_rn(f.x, f.y);
    d2[2 * i + 1] = __floats2bfloat162_rn(f.z, f.w);
}

// ---------------- fused QKV GEMM + bias + (q,k) L2-normalize -----------------
// CTA tile 128x256, 256 threads (8 warps), warp tile 64x64, k=64, 3-stage cp.async
#define APITCH 72
#define BPITCH 264
#define ASTG (128 * APITCH)
#define BSTG (64 * BPITCH)
#define GEMM_SMEM_BYTES ((3 * (ASTG + BSTG)) * 2)

__global__ __launch_bounds__(256) void qkv_kernel(const float* __restrict__ bq,
                                                  const float* __restrict__ bk,
                                                  const float* __restrict__ bv) {
    extern __shared__ __nv_bfloat16 sm[];
    __nv_bfloat16* As = sm;                  // [3][128][APITCH]
    __nv_bfloat16* Bs = sm + 3 * ASTG;       // [3][64][BPITCH]

    int which = blockIdx.x >> 2;
    int n0 = (blockIdx.x & 3) * 256;
    size_t r0 = (size_t)blockIdx.y * 128;
    const __nv_bfloat16* __restrict__ B = g_wb[which];
    __nv_bfloat16* __restrict__ C = which == 0 ? g_q : which == 1 ? g_k : g_v;
    const float* __restrict__ bias = which == 0 ? bq : which == 1 ? bk : bv;

    int tid = threadIdx.x, lane = tid & 31, warp = tid >> 5;
    int wm = (warp & 1) * 64, wn = (warp >> 1) * 64;   // 2 m-groups x 4 n-groups
    int quad = lane >> 3, r8 = lane & 7;
    int arow = tid >> 3, aseg = tid & 7;       // A: 32 rows/pass x 4
    int brow = tid >> 5, bseg = tid & 31;      // B: 8 rows/pass x 8

    float acc[4][8][4];
    #pragma unroll
    for (int a = 0; a < 4; a++)
        #pragma unroll
        for (int b = 0; b < 8; b++)
            #pragma unroll
            for (int c = 0; c < 4; c++) acc[a][b][c] = 0.f;

    auto load_stage = [&](int st, int k0) {
        #pragma unroll
        for (int rr = 0; rr < 4; rr++)
            cp16(&As[st * ASTG + (arow + rr * 32) * APITCH + aseg * 8],
                 &g_xb[(r0 + arow + rr * 32) * INC + k0 + aseg * 8]);
        #pragma unroll
        for (int rr = 0; rr < 8; rr++)
            cp16(&Bs[st * BSTG + (brow + rr * 8) * BPITCH + bseg * 8],
                 &B[(size_t)(k0 + brow + rr * 8) * HD + n0 + bseg * 8]);
        cp_commit();
    };

    load_stage(0, 0);
    load_stage(1, 64);
    #pragma unroll 1
    for (int it = 0; it < 8; it++) {
        int st = it % 3;
        if (it < 7) cp_wait<1>(); else cp_wait<0>();
        __syncthreads();
        if (it + 2 < 8) load_stage((it + 2) % 3, (it + 2) * 64);
        #pragma unroll
        for (int ks = 0; ks < 64; ks += 16) {
            uint32_t af[4][4], bf[4][4];
            #pragma unroll
            for (int mi = 0; mi < 4; mi++)
                ldsm4(af[mi], smem_u32(&As[st * ASTG +
                    (wm + mi * 16 + (quad & 1) * 8 + r8) * APITCH + ks + (quad >> 1) * 8]));
            #pragma unroll
            for (int nj = 0; nj < 4; nj++)
                ldsm4t(bf[nj], smem_u32(&Bs[st * BSTG +
                    (ks + (quad & 1) * 8 + r8) * BPITCH + wn + nj * 16 + (quad >> 1) * 8]));
            #pragma unroll
            for (int mi = 0; mi < 4; mi++)
                #pragma unroll
                for (int nj = 0; nj < 4; nj++) {
                    mma16816(acc[mi][2 * nj],     af[mi], &bf[nj][0]);
                    mma16816(acc[mi][2 * nj + 1], af[mi], &bf[nj][2]);
                }
        }
    }

    int group = lane >> 2, t4 = lane & 3;
    // bias + per-row sum of squares (this thread's 16 cols per row)
    float ss0[4] = {0.f, 0.f, 0.f, 0.f}, ss1[4] = {0.f, 0.f, 0.f, 0.f};
    #pragma unroll
    for (int mi = 0; mi < 4; mi++)
        #pragma unroll
        for (int ni = 0; ni < 8; ni++) {
            int c = n0 + wn + ni * 8 + t4 * 2;
            float b0 = __ldg(&bias[c]), b1 = __ldg(&bias[c + 1]);
            acc[mi][ni][0] += b0; acc[mi][ni][1] += b1;
            acc[mi][ni][2] += b0; acc[mi][ni][3] += b1;
            ss0[mi] += acc[mi][ni][0] * acc[mi][ni][0] + acc[mi][ni][1] * acc[mi][ni][1];
            ss1[mi] += acc[mi][ni][2] * acc[mi][ni][2] + acc[mi][ni][3] * acc[mi][ni][3];
        }

    if (which < 2) {   // normalize q,k rows (tile n-range == one full head)
        #pragma unroll
        for (int mi = 0; mi < 4; mi++) {
            ss0[mi] += __shfl_xor_sync(0xffffffffu, ss0[mi], 1);
            ss0[mi] += __shfl_xor_sync(0xffffffffu, ss0[mi], 2);
            ss1[mi] += __shfl_xor_sync(0xffffffffu, ss1[mi], 1);
            ss1[mi] += __shfl_xor_sync(0xffffffffu, ss1[mi], 2);
        }
        float* ssbuf = (float*)sm;   // stage-0 A region; stages 1,2 active at loop end
        int wng = warp >> 1;         // n-group 0..3
        if (t4 == 0) {
            #pragma unroll
            for (int mi = 0; mi < 4; mi++) {
                ssbuf[wng * 128 + wm + mi * 16 + group]     = ss0[mi];
                ssbuf[wng * 128 + wm + mi * 16 + group + 8] = ss1[mi];
            }
        }
        __syncthreads();
        #pragma unroll
        for (int mi = 0; mi < 4; mi++) {
            int ra = wm + mi * 16 + group;
            float s0 = ssbuf[ra] + ssbuf[128 + ra] + ssbuf[256 + ra] + ssbuf[384 + ra];
            int rb = ra + 8;
            float s1 = ssbuf[rb] + ssbuf[128 + rb] + ssbuf[256 + rb] + ssbuf[384 + rb];
            float i0 = rsqrtf(s0), i1 = rsqrtf(s1);
            #pragma unroll
            for (int ni = 0; ni < 8; ni++) {
                acc[mi][ni][0] *= i0; acc[mi][ni][1] *= i0;
                acc[mi][ni][2] *= i1; acc[mi][ni][3] *= i1;
            }
        }
    }

    #pragma unroll
    for (int mi = 0; mi < 4; mi++) {
        size_t rA = r0 + wm + mi * 16 + group;
        #pragma unroll
        for (int ni = 0; ni < 8; ni++) {
            int c = n0 + wn + ni * 8 + t4 * 2;
            *(__nv_bfloat162*)&C[rA * HD + c] =
                __floats2bfloat162_rn(acc[mi][ni][0], acc[mi][ni][1]);
            *(__nv_bfloat162*)&C[(rA + 8) * HD + c] =
                __floats2bfloat162_rn(acc[mi][ni][2], acc[mi][ni][3]);
        }
    }
}

// ---------------- ksum (column sums of kn) -----------------------------------
__global__ void ksum_p_kernel() {
    int c = blockIdx.x * 256 + threadIdx.x;   // grid.x = 4
    int p = blockIdx.y;                        // grid.y = 64
    size_t r0 = (size_t)p * 1024;
    float s = 0.f;
    for (int r = 0; r < 1024; r++) s += __bfloat162float(g_k[(r0 + r) * HD + c]);
    g_ksum_p[p * HD + c] = s;
}
__global__ void ksum_red_kernel() {
    int c = blockIdx.x * 256 + threadIdx.x;   // grid.x = 4
    float s = 0.f;
    for (int p = 0; p < 64; p++) s += g_ksum_p[p * HD + c];
    g_ksum[c] = s;
}

// ---------------- invden[n,h] = 1/(qn . ksum[h] + N) -------------------------
__global__ void invden_kernel() {
    int wg = blockIdx.x * 8 + (threadIdx.x >> 5);   // wg = n*4+h
    int lane = threadIdx.x & 31, h = wg & 3;
    size_t base = (size_t)wg * 256 + lane * 8;
    uint4 raw = *(const uint4*)&g_q[base];
    __nv_bfloat162* p = (__nv_bfloat162*)&raw;
    const float* ks = &g_ksum[h * 256 + lane * 8];
    float s = 0.f;
    #pragma unroll
    for (int i = 0; i < 4; i++) {
        float2 f = __bfloat1622float2(p[i]);
        s += f.x * ks[2 * i] + f.y * ks[2 * i + 1];
    }
    #pragma unroll
    for (int o = 16; o > 0; o >>= 1) s += __shfl_xor_sync(0xffffffffu, s, o);
    if (lane == 0) g_invden[wg] = 1.f / (s + 65536.f);
}

// ---------------- kv[h] = kn^T @ v, split-K, 3-stage pipeline ----------------
#define KVA_PITCH 136
#define KVB_PITCH 264
#define KVA_STG (64 * KVA_PITCH)
#define KVB_STG (64 * KVB_PITCH)
#define KV_SMEM_BYTES ((3 * (KVA_STG + KVB_STG)) * 2)

__global__ __launch_bounds__(512) void kv_kernel() {
    extern __shared__ __nv_bfloat16 sm[];
    __nv_bfloat16* As = sm;                   // [3][64][KVA_PITCH]  kn[n][m]
    __nv_bfloat16* Bs = sm + 3 * KVA_STG;     // [3][64][KVB_PITCH]  v[n][d]

    int tid = threadIdx.x, lane = tid & 31, warp = tid >> 5;
    int wm = (warp & 3) * 32, wn = (warp >> 2) * 64;
    int h = blockIdx.z & 3;
    int chunk = blockIdx.z >> 2;
    size_t n0 = (size_t)chunk * 4096;
    int m0 = blockIdx.y * 128;
    int quad = lane >> 3, r8 = lane & 7;
    int arow = tid >> 4, aseg = tid & 15;
    int brow = tid >> 5, bseg = tid & 31;

    float acc[2][8][4];
    #pragma unroll
    for (int a = 0; a < 2; a++)
        #pragma unroll
        for (int b = 0; b < 8; b++)
            #pragma unroll
            for (int c = 0; c < 4; c++) acc[a][b][c] = 0.f;

    auto load_stage = [&](int st, int kk) {
        #pragma unroll
        for (int rr = 0; rr < 2; rr++)
            cp16(&As[st * KVA_STG + (arow + rr * 32) * KVA_PITCH + aseg * 8],
                 &g_k[(n0 + kk + arow + rr * 32) * HD + h * 256 + m0 + aseg * 8]);
        #pragma unroll
        for (int rr = 0; rr < 4; rr++)
            cp16(&Bs[st * KVB_STG + (brow + rr * 16) * KVB_PITCH + bseg * 8],
                 &g_v[(n0 + kk + brow + rr * 16) * HD + h * 256 + bseg * 8]);
        cp_commit();
    };

    load_stage(0, 0);
    load_stage(1, 64);
    #pragma unroll 1
    for (int it = 0; it < 64; it++) {
        int st = it % 3;
        if (it < 63) cp_wait<1>(); else cp_wait<0>();
        __syncthreads();
        if (it + 2 < 64) load_stage((it + 2) % 3, (it + 2) * 64);
        #pragma unroll
        for (int ks = 0; ks < 64; ks += 16) {
            uint32_t af[2][4], bf[4][4];
            #pragma unroll
            for (int mi = 0; mi < 2; mi++)
                ldsm4t(af[mi], smem_u32(&As[st * KVA_STG +
                    (ks + (quad >> 1) * 8 + r8) * KVA_PITCH + wm + mi * 16 + (quad & 1) * 8]));
            #pragma unroll
            for (int nj = 0; nj < 4; nj++)
                ldsm4t(bf[nj], smem_u32(&Bs[st * KVB_STG +
                    (ks + (quad & 1) * 8 + r8) * KVB_PITCH + wn + nj * 16 + (quad >> 1) * 8]));
            #pragma unroll
            for (int mi = 0; mi < 2; mi++)
                #pragma unroll
                for (int nj = 0; nj < 4; nj++) {
                    mma16816(acc[mi][2 * nj],     af[mi], &bf[nj][0]);
                    mma16816(acc[mi][2 * nj + 1], af[mi], &bf[nj][2]);
                }
        }
    }
    int group = lane >> 2, t4 = lane & 3;
    float* dst = &g_kv_part[(size_t)chunk * (4 * DIM * DIM) + h * (DIM * DIM)];
    #pragma unroll
    for (int mi = 0; mi < 2; mi++) {
        int rm = m0 + wm + mi * 16 + group;
        #pragma unroll
        for (int ni = 0; ni < 8; ni++) {
            int c = wn + ni * 8 + t4 * 2;
            *(float2*)&dst[rm * 256 + c]       = make_float2(acc[mi][ni][0], acc[mi][ni][1]);
            *(float2*)&dst[(rm + 8) * 256 + c] = make_float2(acc[mi][ni][2], acc[mi][ni][3]);
        }
    }
}

__global__ void kvred_kernel() {
    int i = blockIdx.x * 256 + threadIdx.x;
    float s = 0.f;
    #pragma unroll
    for (int p = 0; p < 16; p++) s += g_kv_part[p * (4 * DIM * DIM) + i];
    g_kvb[i] = __float2bfloat16(s);
}

// ---------------- out = 0.25*((q*invden) @ kv_stacked + rowoff), K=1024 ------
#define OAPITCH 72
#define OASTG (128 * OAPITCH)
#define OBSTG (64 * BPITCH)
#define OUT_SMEM_BYTES ((3 * (OASTG + OBSTG)) * 2)

__global__ __launch_bounds__(512) void out_kernel(float* __restrict__ out) {
    extern __shared__ __nv_bfloat16 sm[];
    __nv_bfloat16* As = sm;
    __nv_bfloat16* Bs = sm + 3 * OASTG;

    size_t r0 = (size_t)blockIdx.y * 128;
    int tid = threadIdx.x, lane = tid & 31, warp = tid >> 5;
    int wm = (warp & 3) * 32, wn = (warp >> 2) * 64;
    int quad = lane >> 3, r8 = lane & 7;
    int arow = tid >> 3, aseg = tid & 7;
    int brow = tid >> 5, bseg = tid & 31;

    float acc[2][8][4];
    #pragma unroll
    for (int a = 0; a < 2; a++)
        #pragma unroll
        for (int b = 0; b < 8; b++)
            #pragma unroll
            for (int c = 0; c < 4; c++) acc[a][b][c] = 0.f;

    uint4 aR[2];
    float invR[2];

    auto ldgA = [&](int kit) {
        int k0 = kit * 64, h = k0 >> 8;
        #pragma unroll
        for (int rr = 0; rr < 2; rr++) {
            size_t row = r0 + arow + rr * 64;
            aR[rr] = *(const uint4*)&g_q[row * HD + k0 + aseg * 8];
            invR[rr] = g_invden[row * 4 + h];
        }
    };
    auto stsA = [&](int kit) {
        int st = kit % 3;
        #pragma unroll
        for (int rr = 0; rr < 2; rr++) {
            __nv_bfloat162* p = (__nv_bfloat162*)&aR[rr];
            float iv = invR[rr];
            uint4 o;
            __nv_bfloat162* q = (__nv_bfloat162*)&o;
            #pragma unroll
            for (int j = 0; j < 4; j++) {
                float2 f = __bfloat1622float2(p[j]);
                q[j] = __floats2bfloat162_rn(f.x * iv, f.y * iv);
            }
            *(uint4*)&As[st * OASTG + (arow + rr * 64) * OAPITCH + aseg * 8] = o;
        }
    };
    auto cpB = [&](int kit) {
        int st = kit % 3, k0 = kit * 64;
        #pragma unroll
        for (int rr = 0; rr < 4; rr++)
            cp16(&Bs[st * OBSTG + (brow + rr * 16) * BPITCH + bseg * 8],
                 &g_kvb[(size_t)(k0 + brow + rr * 16) * 256 + bseg * 8]);
        cp_commit();
    };

    ldgA(0); stsA(0);
    ldgA(1);
    cpB(0); cpB(1);
    #pragma unroll 1
    for (int it = 0; it < 16; it++) {
        int st = it % 3;
        if (it < 15) cp_wait<1>(); else cp_wait<0>();
        __syncthreads();
        if (it + 1 < 16) stsA(it + 1);
        if (it + 2 < 16) { ldgA(it + 2); cpB(it + 2); }
        #pragma unroll
        for (int ks = 0; ks < 64; ks += 16) {
            uint32_t af[2][4], bf[4][4];
            #pragma unroll
            for (int mi = 0; mi < 2; mi++)
                ldsm4(af[mi], smem_u32(&As[st * OASTG +
                    (wm + mi * 16 + (quad & 1) * 8 + r8) * OAPITCH + ks + (quad >> 1) * 8]));
            #pragma unroll
            for (int nj = 0; nj < 4; nj++)
                ldsm4t(bf[nj], smem_u32(&Bs[st * OBSTG +
                    (ks + (quad & 1) * 8 + r8) * BPITCH + wn + nj * 16 + (quad >> 1) * 8]));
            #pragma unroll
            for (int mi = 0; mi < 2; mi++)
                #pragma unroll
                for (int nj = 0; nj < 4; nj++) {
                    mma16816(acc[mi][2 * nj],     af[mi], &bf[nj][0]);
                    mma16816(acc[mi][2 * nj + 1], af[mi], &bf[nj][2]);
                }
        }
    }

    int group = lane >> 2, t4 = lane & 3;
    #pragma unroll
    for (int mi = 0; mi < 2; mi++) {
        size_t rA = r0 + wm + mi * 16 + group;
        size_t rB = rA + 8;
        float ia[4], ib[4];
        #pragma unroll
        for (int h = 0; h < 4; h++) {
            ia[h] = g_invden[rA * 4 + h];
            ib[h] = g_invden[rB * 4 + h];
        }
        #pragma unroll
        for (int ni = 0; ni < 8; ni++) {
            int c = wn + ni * 8 + t4 * 2;
            float roa0 = 0.f, roa1 = 0.f, rob0 = 0.f, rob1 = 0.f;
            #pragma unroll
            for (int h = 0; h < 4; h++) {
                float v0 = __ldg(&g_vsum[h * 256 + c]);
                float v1 = __ldg(&g_vsum[h * 256 + c + 1]);
                roa0 += ia[h] * v0; roa1 += ia[h] * v1;
                rob0 += ib[h] * v0; rob1 += ib[h] * v1;
            }
            *(float2*)&out[rA * 256 + c] =
                make_float2(0.25f * (acc[mi][ni][0] + roa0), 0.25f * (acc[mi][ni][1] + roa1));
            *(float2*)&out[rB * 256 + c] =
                make_float2(0.25f * (acc[mi][ni][2] + rob0), 0.25f * (acc[mi][ni][3] + rob1));
        }
    }
}

// ---------------- launch -----------------------------------------------------
extern "C" void kernel_launch(void* const* d_in, const int* in_sizes, int n_in,
                              void* d_out, int out_size) {
    const float* x  = (const float*)d_in[0];
    const float* Wq = (const float*)d_in[1];
    const float* bq = (const float*)d_in[2];
    const float* Wk = (const float*)d_in[3];
    const float* bk = (const float*)d_in[4];
    const float* Wv = (const float*)d_in[5];
    const float* bv = (const float*)d_in[6];
    float* out = (float*)d_out;

    cudaFuncSetAttribute(qkv_kernel, cudaFuncAttributeMaxDynamicSharedMemorySize, GEMM_SMEM_BYTES);
    cudaFuncSetAttribute(out_kernel, cudaFuncAttributeMaxDynamicSharedMemorySize, OUT_SMEM_BYTES);
    cudaFuncSetAttribute(kv_kernel,  cudaFuncAttributeMaxDynamicSharedMemorySize, KV_SMEM_BYTES);

    cvt_x_kernel<<<256, 256>>>(x);                        // 0
    cvt_w_kernel<<<dim3(512, 3), 256>>>(Wq, Wk, Wv);      // 1
    colsum_red_kernel<<<2, 256>>>();                      // 2
    qkv_kernel<<<dim3(12, 512), 256, GEMM_SMEM_BYTES>>>(bq, bk, bv);   // 3 (profiled)
    vsum_kernel<<<128, 256>>>(Wv, bv);                    // 4
    ksum_p_kernel<<<dim3(4, 64), 256>>>();                // 5
    ksum_red_kernel<<<4, 256>>>();                        // 6
    invden_kernel<<<32768, 256>>>();                      // 7
    kv_kernel<<<dim3(1, 2, 64), 512, KV_SMEM_BYTES>>>();  // 8
    kvred_kernel<<<1024, 256>>>();                        // 9
    out_kernel<<<dim3(1, 512), 512, OUT_SMEM_BYTES>>>(out);  // 10
}